// round 8
// baseline (speedup 1.0000x reference)
#include <cuda_runtime.h>
#include <cstdint>

// 256-bit gather with L2 evict_last. asm VOLATILE: forces ptxas to issue all
// gathers of an edge before any consumer, keeping full MLP=8 per thread
// (the non-volatile version compiled to a 40-reg rolling schedule ~ MLP 4).
__device__ __forceinline__ void ldg256_evict_last_v(const float* p, float* d)
{
    unsigned r0, r1, r2, r3, r4, r5, r6, r7;
    asm volatile(
        "ld.global.nc.L2::evict_last.v8.b32 {%0,%1,%2,%3,%4,%5,%6,%7}, [%8];"
        : "=r"(r0), "=r"(r1), "=r"(r2), "=r"(r3),
          "=r"(r4), "=r"(r5), "=r"(r6), "=r"(r7)
        : "l"(p));
    d[0] = __uint_as_float(r0); d[1] = __uint_as_float(r1);
    d[2] = __uint_as_float(r2); d[3] = __uint_as_float(r3);
    d[4] = __uint_as_float(r4); d[5] = __uint_as_float(r5);
    d[6] = __uint_as_float(r6); d[7] = __uint_as_float(r7);
}

// 4 lanes per edge, 8 edges per warp. Each lane: 4 x 32B chunks from each row
// (chunks sub, sub+4, sub+8, sub+12 of 16) -> 8 independent LDG.256, all
// issued back-to-back (volatile). Reduction: 2 shfl_xor in the 4-lane group.
__global__ __launch_bounds__(256) void edge_dot128_fused_kernel(
    const float* __restrict__ h_user,
    const float* __restrict__ h_item,
    const int* __restrict__ src_clicks,
    const int* __restrict__ dst_clicks,
    const int* __restrict__ src_clickedby,
    const int* __restrict__ dst_clickedby,
    const int* __restrict__ src_follows,
    const int* __restrict__ dst_follows,
    float* __restrict__ out,
    int E)
{
    const int lane = threadIdx.x & 31;
    const int warp_in_block = threadIdx.x >> 5;
    const int sub = lane & 3;        // position within the 4-lane group
    const int group = lane >> 2;     // which of 8 edges this warp handles

    // 64 edges per block (8 warps x 8 edges)
    const int e = blockIdx.x * 64 + warp_in_block * 8 + group;
    const int total = 3 * E;
    if (e >= total) return;

    const float* srcTab;
    const float* dstTab;
    const int* si;
    const int* di;
    int el;
    if (e < E)            { srcTab = h_user; dstTab = h_item; si = src_clicks;    di = dst_clicks;    el = e; }
    else if (e < 2 * E)   { srcTab = h_item; dstTab = h_user; si = src_clickedby; di = dst_clickedby; el = e - E; }
    else                  { srcTab = h_user; dstTab = h_user; si = src_follows;   di = dst_follows;   el = e - 2 * E; }

    // Streaming index loads: read once, evict-first.
    const int s_idx = __ldcs(&si[el]);
    const int d_idx = __ldcs(&di[el]);

    const float* srow = srcTab + (size_t)s_idx * 128;
    const float* drow = dstTab + (size_t)d_idx * 128;

    // All 8 gathers in flight before any math. Interleave a/b so pair 0
    // completes first and FMA chains can start as data lands.
    float a[32], b[32];
    ldg256_evict_last_v(srow + (sub +  0) * 8, a +  0);
    ldg256_evict_last_v(drow + (sub +  0) * 8, b +  0);
    ldg256_evict_last_v(srow + (sub +  4) * 8, a +  8);
    ldg256_evict_last_v(drow + (sub +  4) * 8, b +  8);
    ldg256_evict_last_v(srow + (sub +  8) * 8, a + 16);
    ldg256_evict_last_v(drow + (sub +  8) * 8, b + 16);
    ldg256_evict_last_v(srow + (sub + 12) * 8, a + 24);
    ldg256_evict_last_v(drow + (sub + 12) * 8, b + 24);

    // 4 independent accumulation chains (one per chunk pair).
    float s0 = 0.f, s1 = 0.f, s2 = 0.f, s3 = 0.f;
    #pragma unroll
    for (int i = 0; i < 8; i++) {
        s0 += a[i]      * b[i];
        s1 += a[i + 8]  * b[i + 8];
        s2 += a[i + 16] * b[i + 16];
        s3 += a[i + 24] * b[i + 24];
    }
    float sum = (s0 + s1) + (s2 + s3);

    // Reduce across the 4-lane group
    sum += __shfl_xor_sync(0xFFFFFFFFu, sum, 1);
    sum += __shfl_xor_sync(0xFFFFFFFFu, sum, 2);

    // Streaming store: don't churn the L2 with output lines.
    if (sub == 0) __stcs(&out[e], sum);
}

extern "C" void kernel_launch(void* const* d_in, const int* in_sizes, int n_in,
                              void* d_out, int out_size)
{
    const float* h_user = (const float*)d_in[0];
    const float* h_item = (const float*)d_in[1];
    const int* src_clicks    = (const int*)d_in[2];
    const int* dst_clicks    = (const int*)d_in[3];
    const int* src_clickedby = (const int*)d_in[4];
    const int* dst_clickedby = (const int*)d_in[5];
    const int* src_follows   = (const int*)d_in[6];
    const int* dst_follows   = (const int*)d_in[7];
    float* out = (float*)d_out;

    const int E = in_sizes[2];  // edges per etype (500000)
    const int total = 3 * E;

    const int threads = 256;            // 8 warps x 8 edges = 64 edges/block
    const int blocks = (total + 63) / 64;

    edge_dot128_fused_kernel<<<blocks, threads>>>(
        h_user, h_item,
        src_clicks, dst_clicks,
        src_clickedby, dst_clickedby,
        src_follows, dst_follows,
        out, E);
}